// round 10
// baseline (speedup 1.0000x reference)
#include <cuda_runtime.h>
#include <cstdint>
#include <math.h>

// CropAndResize: x [B,H,W,C=4] fp32, boxes [B,4] (y1,x1,y2,x2 in [0,1]),
// output [B,crop,crop,4] fp32 bilinear.
//
// One block per (output row, batch). The two source rows (t, t+1) and the
// x-span [l0 .. lN+1] are block-uniform, so the block stages both row spans
// into smem with TWO cp.async.bulk (TMA/UBLKCP) copies behind an mbarrier,
// then threads bilinear-lerp from smem and store coalesced.
//
// Why: rounds 1/3/9 all pinned at ~14.8us = 55MB / 3.2TB/s, invariant to
// occupancy x MLP -> the SM-side outstanding-LDG line budget (~64 lines/SM
// x 128B / ~600cyc DRAM lat ~= 3.2TB/s chip) caps the tracked-LDG read
// path. cp.async.bulk bypasses that tracking (TMA path, LTS-capped at
// ~12TB/s), so reads stop being the bottleneck.

#define TPB 256
#define SPAN_MAX 1024   // span = lN+2-l0 <= W-2+2-0 = 1024 float4

__global__ __launch_bounds__(TPB)
void crop_resize_bulk_kernel(const float* __restrict__ x,
                             const float* __restrict__ boxes,
                             float* __restrict__ out,
                             int H, int W, int crop) {
    __shared__ alignas(16) float4 rows[2][SPAN_MAX];
    __shared__ uint64_t mbar;

    const int r = blockIdx.x;   // output row  (uniform)
    const int b = blockIdx.y;   // batch       (uniform)
    const int tid = threadIdx.x;

    const float4 bx = __ldg((const float4*)boxes + b);   // y1,x1,y2,x2
    const float inv = 1.0f / (float)(crop - 1);
    const float hm1 = (float)(H - 1);
    const float wm1 = (float)(W - 1);

    const float in_y = (bx.x + (float)r * inv * (bx.z - bx.x)) * hm1;
    const bool valid_y = (in_y >= 0.0f) && (in_y <= hm1);

    float4* __restrict__ outrow =
        (float4*)(out) + ((size_t)b * crop + r) * crop;

    if (!valid_y) {                       // uniform across block
        const float4 z = make_float4(0.f, 0.f, 0.f, 0.f);
        for (int c = tid; c < crop; c += TPB) outrow[c] = z;
        return;
    }

    // clamp form t in [0,H-2], yl = in_y - t (validated vs reference in R8/R9)
    const int t = min(max((int)in_y, 0), H - 2);
    const float yl = in_y - (float)t;

    const float xoff = bx.y * wm1;
    const float xscl = inv * (bx.w - bx.y) * wm1;   // >= 0 (xs sorted)

    // block-uniform x-span: l is monotonic in c, so [l(0) .. l(crop-1)+1]
    const int l0 = min(max((int)xoff, 0), W - 2);
    const int lN = min(max((int)fmaf((float)(crop - 1), xscl, xoff), 0), W - 2);
    const int span = lN + 2 - l0;                   // 2..1024 float4
    const unsigned bytes = (unsigned)span * 16u;

    const float4* __restrict__ rowT =
        (const float4*)(x) + ((size_t)b * H + t) * W + l0;

    const unsigned mb = (unsigned)__cvta_generic_to_shared(&mbar);
    if (tid == 0) {
        asm volatile("mbarrier.init.shared.b64 [%0], 1;" :: "r"(mb) : "memory");
    }
    __syncthreads();

    if (tid == 0) {
        asm volatile("mbarrier.arrive.expect_tx.shared.b64 _, [%0], %1;"
                     :: "r"(mb), "r"(2u * bytes) : "memory");
        const unsigned d0 = (unsigned)__cvta_generic_to_shared(&rows[0][0]);
        const unsigned d1 = (unsigned)__cvta_generic_to_shared(&rows[1][0]);
        asm volatile(
            "cp.async.bulk.shared::cta.global.mbarrier::complete_tx::bytes "
            "[%0], [%1], %2, [%3];"
            :: "r"(d0), "l"(rowT), "r"(bytes), "r"(mb) : "memory");
        asm volatile(
            "cp.async.bulk.shared::cta.global.mbarrier::complete_tx::bytes "
            "[%0], [%1], %2, [%3];"
            :: "r"(d1), "l"(rowT + W), "r"(bytes), "r"(mb) : "memory");
    }

    // wait, phase 0 (barrier used exactly once per block)
    asm volatile(
        "{\n\t"
        ".reg .pred P;\n\t"
        "WAIT_%=:\n\t"
        "mbarrier.try_wait.parity.acquire.cta.shared::cta.b64 P, [%0], 0, 0x989680;\n\t"
        "@P bra DONE_%=;\n\t"
        "bra WAIT_%=;\n\t"
        "DONE_%=:\n\t"
        "}"
        :: "r"(mb) : "memory");

    for (int c = tid; c < crop; c += TPB) {
        const float in_x = fmaf((float)c, xscl, xoff);
        const bool valid = (in_x >= 0.0f) && (in_x <= wm1);

        const int l = min(max((int)in_x, 0), W - 2);
        const float xl = in_x - (float)l;
        const int j = l - l0;                       // in [0, span-2]

        const float4 tl4 = rows[0][j];
        const float4 tr4 = rows[0][j + 1];
        const float4 bl4 = rows[1][j];
        const float4 br4 = rows[1][j + 1];

        float4 res = make_float4(0.f, 0.f, 0.f, 0.f);
        if (valid) {
            const float tx0 = fmaf(tr4.x - tl4.x, xl, tl4.x);
            const float ty0 = fmaf(tr4.y - tl4.y, xl, tl4.y);
            const float tz0 = fmaf(tr4.z - tl4.z, xl, tl4.z);
            const float tw0 = fmaf(tr4.w - tl4.w, xl, tl4.w);
            const float bx0 = fmaf(br4.x - bl4.x, xl, bl4.x);
            const float by0 = fmaf(br4.y - bl4.y, xl, bl4.y);
            const float bz0 = fmaf(br4.z - bl4.z, xl, bl4.z);
            const float bw0 = fmaf(br4.w - bl4.w, xl, bl4.w);
            res.x = fmaf(bx0 - tx0, yl, tx0);
            res.y = fmaf(by0 - ty0, yl, ty0);
            res.z = fmaf(bz0 - tz0, yl, tz0);
            res.w = fmaf(bw0 - tw0, yl, tw0);
        }
        outrow[c] = res;
    }
}

extern "C" void kernel_launch(void* const* d_in, const int* in_sizes, int n_in,
                              void* d_out, int out_size) {
    const float* x     = (const float*)d_in[0];
    const float* boxes = (const float*)d_in[1];
    float* out = (float*)d_out;

    const int B = in_sizes[1] / 4;          // boxes is [B,4]
    const int C = 4;
    const long long hw = (long long)in_sizes[0] / ((long long)B * C);
    int H = (int)(sqrt((double)hw) + 0.5);
    int W = H;
    const long long cc = (long long)out_size / ((long long)B * C);
    int crop = (int)(sqrt((double)cc) + 0.5);

    dim3 grid(crop, B);
    crop_resize_bulk_kernel<<<grid, TPB>>>(x, boxes, out, H, W, crop);
}

// round 11
// speedup vs baseline: 1.0118x; 1.0118x over previous
#include <cuda_runtime.h>
#include <cstdint>
#include <math.h>

// CropAndResize: x [B,H,W,C=4] fp32, boxes [B,4] (y1,x1,y2,x2 in [0,1]),
// output [B,crop,crop,4] fp32 bilinear.
//
// Pipelined bulk-TMA version of R10: each block owns RPB=4 output rows of
// one batch (same x-span, block-uniform). Two smem stages, each holding a
// (row t, row t+1) span pair; cp.async.bulk double-buffers row-pair loads
// behind per-stage mbarriers while threads bilinear-lerp the previous pair
// from smem and store coalesced. Fixes R10's per-block latency
// serialization (its reads/traffic were already optimal: 55.6MB == R1).

#define TPB 256
#define RPB 4          // output rows per block (2-stage pipeline)
#define SPAN_CAP 1024  // span = lN+2-l0 <= W (float4 units)

extern __shared__ float4 sbuf[];   // [2 stages][2 rows][SPAN_CAP]

__device__ __forceinline__ float4* stage_ptr(int s, int row) {
    return sbuf + ((s * 2 + row) * SPAN_CAP);
}

__global__ __launch_bounds__(TPB)
void crop_resize_pipe_kernel(const float* __restrict__ x,
                             const float* __restrict__ boxes,
                             float* __restrict__ out,
                             int H, int W, int crop) {
    __shared__ uint64_t mbar[2];

    const int r0  = blockIdx.x * RPB;
    const int b   = blockIdx.y;
    const int tid = threadIdx.x;

    const float4 bx = __ldg((const float4*)boxes + b);   // y1,x1,y2,x2
    const float inv = 1.0f / (float)(crop - 1);
    const float hm1 = (float)(H - 1);
    const float wm1 = (float)(W - 1);

    const float yoff = bx.x * hm1;
    const float yscl = inv * (bx.z - bx.x) * hm1;   // >= 0 (ys sorted)
    const float xoff = bx.y * wm1;
    const float xscl = inv * (bx.w - bx.y) * wm1;   // >= 0 (xs sorted)

    // block-uniform x-span (l monotonic in c)
    const int l0 = min(max((int)xoff, 0), W - 2);
    const int lN = min(max((int)fmaf((float)(crop - 1), xscl, xoff), 0), W - 2);
    const int span  = lN + 2 - l0;                  // 2..1024 float4
    const unsigned bytes = (unsigned)span * 16u;

    const float4* __restrict__ xrow0 = (const float4*)(x) + (size_t)b * H * W + l0;

    const unsigned mb0 = (unsigned)__cvta_generic_to_shared(&mbar[0]);
    const unsigned mb1 = (unsigned)__cvta_generic_to_shared(&mbar[1]);

    if (tid == 0) {
        asm volatile("mbarrier.init.shared.b64 [%0], 1;" :: "r"(mb0) : "memory");
        asm volatile("mbarrier.init.shared.b64 [%0], 1;" :: "r"(mb1) : "memory");
    }
    __syncthreads();

    // issue row-pair load for pipeline slot i (row r0+i) into stage i&1
    auto issue = [&](int i) {
        const int rr = min(r0 + i, crop - 1);
        const float in_y = fmaf((float)rr, yscl, yoff);
        const int t = min(max((int)in_y, 0), H - 2);
        const float4* src = xrow0 + (size_t)t * W;
        const unsigned mb = (i & 1) ? mb1 : mb0;
        asm volatile("mbarrier.arrive.expect_tx.shared.b64 _, [%0], %1;"
                     :: "r"(mb), "r"(2u * bytes) : "memory");
        const unsigned d0 = (unsigned)__cvta_generic_to_shared(stage_ptr(i & 1, 0));
        const unsigned d1 = (unsigned)__cvta_generic_to_shared(stage_ptr(i & 1, 1));
        asm volatile(
            "cp.async.bulk.shared::cta.global.mbarrier::complete_tx::bytes "
            "[%0], [%1], %2, [%3];"
            :: "r"(d0), "l"(src), "r"(bytes), "r"(mb) : "memory");
        asm volatile(
            "cp.async.bulk.shared::cta.global.mbarrier::complete_tx::bytes "
            "[%0], [%1], %2, [%3];"
            :: "r"(d1), "l"(src + W), "r"(bytes), "r"(mb) : "memory");
    };

    if (tid == 0) { issue(0); issue(1); }

    #pragma unroll
    for (int i = 0; i < RPB; i++) {
        const unsigned mb = (i & 1) ? mb1 : mb0;
        const unsigned ph = (unsigned)((i >> 1) & 1);
        asm volatile(
            "{\n\t"
            ".reg .pred P;\n\t"
            "WAIT_%=:\n\t"
            "mbarrier.try_wait.parity.acquire.cta.shared::cta.b64 P, [%0], %1, 0x989680;\n\t"
            "@P bra DONE_%=;\n\t"
            "bra WAIT_%=;\n\t"
            "DONE_%=:\n\t"
            "}"
            :: "r"(mb), "r"(ph) : "memory");

        const int r = r0 + i;
        if (r < crop) {
            const float in_y = fmaf((float)r, yscl, yoff);
            const bool valid_y = (in_y >= 0.0f) && (in_y <= hm1);
            const int t = min(max((int)in_y, 0), H - 2);
            const float yl = in_y - (float)t;

            const float4* __restrict__ rT = stage_ptr(i & 1, 0);
            const float4* __restrict__ rB = stage_ptr(i & 1, 1);
            float4* __restrict__ outrow =
                (float4*)(out) + ((size_t)b * crop + r) * crop;

            for (int c = tid; c < crop; c += TPB) {
                const float in_x = fmaf((float)c, xscl, xoff);
                const bool valid = valid_y && (in_x >= 0.0f) && (in_x <= wm1);

                const int l = min(max((int)in_x, 0), W - 2);
                const float xl = in_x - (float)l;
                const int j = l - l0;

                const float4 tl4 = rT[j];
                const float4 tr4 = rT[j + 1];
                const float4 bl4 = rB[j];
                const float4 br4 = rB[j + 1];

                float4 res = make_float4(0.f, 0.f, 0.f, 0.f);
                if (valid) {
                    const float tx0 = fmaf(tr4.x - tl4.x, xl, tl4.x);
                    const float ty0 = fmaf(tr4.y - tl4.y, xl, tl4.y);
                    const float tz0 = fmaf(tr4.z - tl4.z, xl, tl4.z);
                    const float tw0 = fmaf(tr4.w - tl4.w, xl, tl4.w);
                    const float bx0 = fmaf(br4.x - bl4.x, xl, bl4.x);
                    const float by0 = fmaf(br4.y - bl4.y, xl, bl4.y);
                    const float bz0 = fmaf(br4.z - bl4.z, xl, bl4.z);
                    const float bw0 = fmaf(br4.w - bl4.w, xl, bl4.w);
                    res.x = fmaf(bx0 - tx0, yl, tx0);
                    res.y = fmaf(by0 - ty0, yl, ty0);
                    res.z = fmaf(bz0 - tz0, yl, tz0);
                    res.w = fmaf(bw0 - tw0, yl, tw0);
                }
                outrow[c] = res;
            }
        }

        __syncthreads();                 // all reads of this stage done
        if (tid == 0 && (i + 2) < RPB) issue(i + 2);
    }
}

extern "C" void kernel_launch(void* const* d_in, const int* in_sizes, int n_in,
                              void* d_out, int out_size) {
    const float* x     = (const float*)d_in[0];
    const float* boxes = (const float*)d_in[1];
    float* out = (float*)d_out;

    const int B = in_sizes[1] / 4;          // boxes is [B,4]
    const int C = 4;
    const long long hw = (long long)in_sizes[0] / ((long long)B * C);
    int H = (int)(sqrt((double)hw) + 0.5);
    int W = H;
    const long long cc = (long long)out_size / ((long long)B * C);
    int crop = (int)(sqrt((double)cc) + 0.5);

    const int smem_bytes = 2 * 2 * SPAN_CAP * 16;   // 64 KB
    cudaFuncSetAttribute(crop_resize_pipe_kernel,
                         cudaFuncAttributeMaxDynamicSharedMemorySize, smem_bytes);

    dim3 grid((crop + RPB - 1) / RPB, B);
    crop_resize_pipe_kernel<<<grid, TPB, smem_bytes>>>(x, boxes, out, H, W, crop);
}